// round 7
// baseline (speedup 1.0000x reference)
#include <cuda_runtime.h>
#include <math.h>
#include <stdint.h>

#define TDIM 4096
#define DDIM 768
#define EDIM 1536
#define BDIM 8
#define MROWS (BDIM * TDIM)

__device__ float g_h[(size_t)MROWS * DDIM];
__device__ float g_val[(size_t)MROWS * EDIM];
__device__ float g_u[(size_t)MROWS * EDIM];
__device__ float g_out[(size_t)MROWS * DDIM];
__device__ float g_v[(size_t)MROWS * DDIM];
__device__ float g_intra[(size_t)MROWS * DDIM];
__device__ float g_interp[3 * (size_t)MROWS * DDIM];

// ---------------- rmsnorm ----------------
__global__ void __launch_bounds__(256) rmsnorm_kernel(const float* __restrict__ x,
                                                      const float* __restrict__ w,
                                                      float* __restrict__ h)
{
    const int m = blockIdx.x;
    const float* row = x + (size_t)m * DDIM;
    float s = 0.f;
#pragma unroll
    for (int i = 0; i < 3; i++) { float v = row[threadIdx.x + i * 256]; s += v * v; }
#pragma unroll
    for (int o = 16; o; o >>= 1) s += __shfl_xor_sync(0xffffffffu, s, o);
    __shared__ float red[8];
    if ((threadIdx.x & 31) == 0) red[threadIdx.x >> 5] = s;
    __syncthreads();
    float tot = 0.f;
#pragma unroll
    for (int i = 0; i < 8; i++) tot += red[i];
    const float rs = rsqrtf(tot / (float)DDIM + 1e-5f);
    float* hrow = h + (size_t)m * DDIM;
#pragma unroll
    for (int i = 0; i < 3; i++) {
        int idx = threadIdx.x + i * 256;
        hrow[idx] = row[idx] * rs * w[idx];
    }
}

// ---------- NT SGEMM: C[M,N] = A[M,K] @ B[N,K]^T, 128x128x16 tiles ----------
// MODE 0: plain. MODE 1: gate/conv epilogue (P0=val,P1=conv_w,P2=conv_b).
// MODE 2: A-load sums A+P0+P1+P2; epilogue C = P3 + P4 + exp(*P5)*acc.
template <int MODE>
__global__ void __launch_bounds__(256, 2) gemm_nt(
    const float* __restrict__ A, const float* __restrict__ Bw,
    float* __restrict__ C, int N, int K,
    const float* __restrict__ P0, const float* __restrict__ P1,
    const float* __restrict__ P2, const float* __restrict__ P3,
    const float* __restrict__ P4, const float* __restrict__ P5)
{
    __shared__ float As[2][16][128];
    __shared__ float Bs[2][16][128];
    const int tid = threadIdx.x;
    const int bm = blockIdx.y * 128, bn = blockIdx.x * 128;
    const int KT = K >> 4;
    float4 ra[2], rb[2];

    auto fetch = [&](int kt) {
#pragma unroll
        for (int i = 0; i < 2; i++) {
            int id = tid + i * 256, row = id >> 2, col = (id & 3) << 2;
            size_t aoff = (size_t)(bm + row) * K + (size_t)kt * 16 + col;
            float4 v = *(const float4*)(A + aoff);
            if (MODE == 2) {
                float4 a1 = *(const float4*)(P0 + aoff);
                float4 a2 = *(const float4*)(P1 + aoff);
                float4 a3 = *(const float4*)(P2 + aoff);
                v.x += a1.x + a2.x + a3.x; v.y += a1.y + a2.y + a3.y;
                v.z += a1.z + a2.z + a3.z; v.w += a1.w + a2.w + a3.w;
            }
            ra[i] = v;
            rb[i] = *(const float4*)(Bw + (size_t)(bn + row) * K + (size_t)kt * 16 + col);
        }
    };
    auto stor = [&](int buf) {
#pragma unroll
        for (int i = 0; i < 2; i++) {
            int id = tid + i * 256, row = id >> 2, col = (id & 3) << 2;
            As[buf][col + 0][row] = ra[i].x; As[buf][col + 1][row] = ra[i].y;
            As[buf][col + 2][row] = ra[i].z; As[buf][col + 3][row] = ra[i].w;
            Bs[buf][col + 0][row] = rb[i].x; Bs[buf][col + 1][row] = rb[i].y;
            Bs[buf][col + 2][row] = rb[i].z; Bs[buf][col + 3][row] = rb[i].w;
        }
    };

    const int tx = tid & 15, ty = tid >> 4;
    const int m0 = ty * 8, n0 = tx * 8;
    float acc[8][8];
#pragma unroll
    for (int i = 0; i < 8; i++)
#pragma unroll
        for (int j = 0; j < 8; j++) acc[i][j] = 0.f;

    fetch(0); stor(0); __syncthreads();
    int buf = 0;
    for (int kt = 0; kt < KT; kt++) {
        if (kt + 1 < KT) fetch(kt + 1);
#pragma unroll
        for (int k = 0; k < 16; k++) {
            float a[8], b[8];
            *(float4*)&a[0] = *(const float4*)&As[buf][k][m0];
            *(float4*)&a[4] = *(const float4*)&As[buf][k][m0 + 4];
            *(float4*)&b[0] = *(const float4*)&Bs[buf][k][n0];
            *(float4*)&b[4] = *(const float4*)&Bs[buf][k][n0 + 4];
#pragma unroll
            for (int i = 0; i < 8; i++)
#pragma unroll
                for (int j = 0; j < 8; j++) acc[i][j] += a[i] * b[j];
        }
        if (kt + 1 < KT) stor(buf ^ 1);
        __syncthreads();
        buf ^= 1;
    }

    float alpha = 0.f;
    if (MODE == 2) alpha = expf(P5[0]);
#pragma unroll
    for (int i = 0; i < 8; i++) {
        const int m = bm + m0 + i;
#pragma unroll
        for (int j = 0; j < 8; j++) {
            const int n = bn + n0 + j;
            const size_t idx = (size_t)m * N + n;
            float r = acc[i][j];
            if (MODE == 0) {
                C[idx] = r;
            } else if (MODE == 1) {
                float g = r / (1.f + expf(-r));        // silu(gate)
                int t = m & (TDIM - 1);
                float cv = P2[n];
                const float* cwn = P1 + (size_t)n * 4;
#pragma unroll
                for (int q = 0; q < 4; q++) {
                    int tt = t - 3 + q;
                    if (tt >= 0) cv += cwn[q] * P0[(size_t)(m - 3 + q) * N + n];
                }
                float sv = cv / (1.f + expf(-cv));     // silu(conv)
                C[idx] = sv * g;
            } else {
                C[idx] = P3[idx] + P4[idx] + alpha * r;
            }
        }
    }
}

// -------- chunk-local: S = r k^T (k shifted), intra = (S .* M) v --------
__global__ void __launch_bounds__(256) intra_kernel(const float* __restrict__ outp,
                                                    const float* __restrict__ vp,
                                                    float* __restrict__ intrap,
                                                    const float* __restrict__ decayp)
{
    __shared__ float Rt[16][68];
    __shared__ float Kt[16][68];
    __shared__ float SMt[64][68];
    __shared__ float Vs[64][68];

    const int ch = blockIdx.x, b = blockIdx.y;
    const int t0 = ch * 64;
    const int tid = threadIdx.x;
    const int tx = tid & 15, ty = tid >> 4;
    const int lc = tid >> 2, lq = tid & 3;
    const float gamma = 1.f / (1.f + expf(-decayp[0]));
    const float lg = logf(gamma);

    const float* outB = outp + (size_t)b * TDIM * DDIM;
    const float* vB = vp + (size_t)b * TDIM * DDIM;

    const int c0 = ty * 4, e0 = tx * 4;
    float acc[4][4];
#pragma unroll
    for (int i = 0; i < 4; i++)
#pragma unroll
        for (int j = 0; j < 4; j++) acc[i][j] = 0.f;

    for (int ks = 0; ks < DDIM / 16; ks++) {
        {
            float4 r4 = *(const float4*)(outB + (size_t)(t0 + lc) * DDIM + ks * 16 + lq * 4);
            Rt[lq * 4 + 0][lc] = r4.x; Rt[lq * 4 + 1][lc] = r4.y;
            Rt[lq * 4 + 2][lc] = r4.z; Rt[lq * 4 + 3][lc] = r4.w;
            int tk = t0 + lc - 1;
            float4 k4 = make_float4(0.f, 0.f, 0.f, 0.f);
            if (tk >= 0) k4 = *(const float4*)(outB + (size_t)tk * DDIM + ks * 16 + lq * 4);
            Kt[lq * 4 + 0][lc] = k4.x; Kt[lq * 4 + 1][lc] = k4.y;
            Kt[lq * 4 + 2][lc] = k4.z; Kt[lq * 4 + 3][lc] = k4.w;
        }
        __syncthreads();
#pragma unroll
        for (int k = 0; k < 16; k++) {
            float4 a = *(const float4*)&Rt[k][c0];
            float4 bb = *(const float4*)&Kt[k][e0];
            acc[0][0] += a.x * bb.x; acc[0][1] += a.x * bb.y; acc[0][2] += a.x * bb.z; acc[0][3] += a.x * bb.w;
            acc[1][0] += a.y * bb.x; acc[1][1] += a.y * bb.y; acc[1][2] += a.y * bb.z; acc[1][3] += a.y * bb.w;
            acc[2][0] += a.z * bb.x; acc[2][1] += a.z * bb.y; acc[2][2] += a.z * bb.z; acc[2][3] += a.z * bb.w;
            acc[3][0] += a.w * bb.x; acc[3][1] += a.w * bb.y; acc[3][2] += a.w * bb.z; acc[3][3] += a.w * bb.w;
        }
        __syncthreads();
    }
#pragma unroll
    for (int i = 0; i < 4; i++)
#pragma unroll
        for (int j = 0; j < 4; j++) {
            int c = c0 + i, e = e0 + j;
            float mval = (c > e) ? expf(lg * (float)(c - 1 - e)) : 0.f;
            SMt[e][c] = acc[i][j] * mval;
        }
    __syncthreads();

    for (int db = 0; db < DDIM / 64; db++) {
#pragma unroll
        for (int i = 0; i < 4; i++)
            *(float4*)&Vs[lc][lq * 16 + i * 4] =
                *(const float4*)(vB + (size_t)(t0 + lc) * DDIM + db * 64 + lq * 16 + i * 4);
        __syncthreads();
        float a2[4][4];
#pragma unroll
        for (int i = 0; i < 4; i++)
#pragma unroll
            for (int j = 0; j < 4; j++) a2[i][j] = 0.f;
#pragma unroll 8
        for (int e = 0; e < 64; e++) {
            float4 a = *(const float4*)&SMt[e][c0];
            float4 bb = *(const float4*)&Vs[e][tx * 4];
            a2[0][0] += a.x * bb.x; a2[0][1] += a.x * bb.y; a2[0][2] += a.x * bb.z; a2[0][3] += a.x * bb.w;
            a2[1][0] += a.y * bb.x; a2[1][1] += a.y * bb.y; a2[1][2] += a.y * bb.z; a2[1][3] += a.y * bb.w;
            a2[2][0] += a.z * bb.x; a2[2][1] += a.z * bb.y; a2[2][2] += a.z * bb.z; a2[2][3] += a.z * bb.w;
            a2[3][0] += a.w * bb.x; a2[3][1] += a.w * bb.y; a2[3][2] += a.w * bb.z; a2[3][3] += a.w * bb.w;
        }
#pragma unroll
        for (int i = 0; i < 4; i++)
            *(float4*)(intrap + (size_t)b * TDIM * DDIM + (size_t)(t0 + c0 + i) * DDIM + db * 64 + tx * 4)
                = make_float4(a2[i][0], a2[i][1], a2[i][2], a2[i][3]);
        __syncthreads();
    }
}

// -------- recurrent scan: W tile [kk 256][dv 64] per CTA, sequential over 64 chunks --------
#define SCAN_SMEM_FLOATS (256 * 64 + 256 * 68 + 64 * 260 + 64 * 68)

__global__ void __launch_bounds__(256) scan_kernel(const float* __restrict__ outp,
                                                   const float* __restrict__ vp,
                                                   float* __restrict__ interp,
                                                   const float* __restrict__ decayp)
{
    extern __shared__ float sm[];
    float* Wt = sm;                   // [256][64]   W[dv,kk] stored [kk][dv]
    float* Rt = Wt + 256 * 64;        // [256][68]
    float* Ks = Rt + 256 * 68;        // [64][260]
    float* Vg = Ks + 64 * 260;        // [64][68]

    const int slab = blockIdx.x, dvb = blockIdx.y, b = blockIdx.z;
    const int kkbase = slab * 256, dvbase = dvb * 64;
    const int tid = threadIdx.x;
    const float gamma = 1.f / (1.f + expf(-decayp[0]));
    const float lg = logf(gamma);
    const float gC = expf(lg * 64.f);

    for (int i = tid; i < 256 * 64; i += 256) Wt[i] = 0.f;

    const float* outB = outp + (size_t)b * TDIM * DDIM;
    const float* vB = vp + (size_t)b * TDIM * DDIM;
    float* ipB = interp + (size_t)slab * ((size_t)MROWS * DDIM) + (size_t)b * TDIM * DDIM;

    const int tx = tid & 15, ty = tid >> 4;
    const int lc = tid >> 2, lq = tid & 3;
    const float gwc = expf(lg * (float)(63 - lc));
    __syncthreads();

    for (int ch = 0; ch < 64; ch++) {
        const int t0 = ch * 64;
        {
            const float* rrow = outB + (size_t)(t0 + lc) * DDIM + kkbase + lq * 64;
#pragma unroll
            for (int i = 0; i < 16; i++) {
                float4 v4 = *(const float4*)(rrow + i * 4);
                int kk = lq * 64 + i * 4;
                Rt[(kk + 0) * 68 + lc] = v4.x; Rt[(kk + 1) * 68 + lc] = v4.y;
                Rt[(kk + 2) * 68 + lc] = v4.z; Rt[(kk + 3) * 68 + lc] = v4.w;
            }
            int tk = t0 + lc - 1;
            if (tk >= 0) {
                const float* krow = outB + (size_t)tk * DDIM + kkbase + lq * 64;
#pragma unroll
                for (int i = 0; i < 16; i++)
                    *(float4*)&Ks[lc * 260 + lq * 64 + i * 4] = *(const float4*)(krow + i * 4);
            } else {
                float4 z = make_float4(0.f, 0.f, 0.f, 0.f);
#pragma unroll
                for (int i = 0; i < 16; i++)
                    *(float4*)&Ks[lc * 260 + lq * 64 + i * 4] = z;
            }
            const float* vrow = vB + (size_t)(t0 + lc) * DDIM + dvbase + lq * 16;
#pragma unroll
            for (int i = 0; i < 4; i++) {
                float4 v4 = *(const float4*)(vrow + i * 4);
                v4.x *= gwc; v4.y *= gwc; v4.z *= gwc; v4.w *= gwc;
                *(float4*)&Vg[lc * 68 + lq * 16 + i * 4] = v4;
            }
        }
        __syncthreads();
        // phase A: inter[c,dv] = gp[c] * sum_kk r[c,kk] * W[dv,kk]
        {
            const int c0 = ty * 4, dv0 = tx * 4;
            float acc[4][4];
#pragma unroll
            for (int i = 0; i < 4; i++)
#pragma unroll
                for (int j = 0; j < 4; j++) acc[i][j] = 0.f;
#pragma unroll 4
            for (int k = 0; k < 256; k++) {
                float4 a = *(const float4*)&Rt[k * 68 + c0];
                float4 w = *(const float4*)&Wt[k * 64 + dv0];
                acc[0][0] += a.x * w.x; acc[0][1] += a.x * w.y; acc[0][2] += a.x * w.z; acc[0][3] += a.x * w.w;
                acc[1][0] += a.y * w.x; acc[1][1] += a.y * w.y; acc[1][2] += a.y * w.z; acc[1][3] += a.y * w.w;
                acc[2][0] += a.z * w.x; acc[2][1] += a.z * w.y; acc[2][2] += a.z * w.z; acc[2][3] += a.z * w.w;
                acc[3][0] += a.w * w.x; acc[3][1] += a.w * w.y; acc[3][2] += a.w * w.z; acc[3][3] += a.w * w.w;
            }
#pragma unroll
            for (int i = 0; i < 4; i++) {
                float gpc = expf(lg * (float)(c0 + i));
                *(float4*)(ipB + (size_t)(t0 + c0 + i) * DDIM + dvbase + dv0) =
                    make_float4(acc[i][0] * gpc, acc[i][1] * gpc, acc[i][2] * gpc, acc[i][3] * gpc);
            }
        }
        __syncthreads();
        // phase B: W[dv,kk] = gC*W + sum_c vg[c,dv]*k[c,kk]
        {
            const int dv0 = tx * 4, kk0 = ty * 16;
            float acc[16][4];
#pragma unroll
            for (int i = 0; i < 16; i++)
#pragma unroll
                for (int j = 0; j < 4; j++) acc[i][j] = 0.f;
#pragma unroll 4
            for (int c = 0; c < 64; c++) {
                float4 v4 = *(const float4*)&Vg[c * 68 + dv0];
#pragma unroll
                for (int ii = 0; ii < 4; ii++) {
                    float4 k4 = *(const float4*)&Ks[c * 260 + kk0 + ii * 4];
                    int r = ii * 4;
                    acc[r + 0][0] += k4.x * v4.x; acc[r + 0][1] += k4.x * v4.y; acc[r + 0][2] += k4.x * v4.z; acc[r + 0][3] += k4.x * v4.w;
                    acc[r + 1][0] += k4.y * v4.x; acc[r + 1][1] += k4.y * v4.y; acc[r + 1][2] += k4.y * v4.z; acc[r + 1][3] += k4.y * v4.w;
                    acc[r + 2][0] += k4.z * v4.x; acc[r + 2][1] += k4.z * v4.y; acc[r + 2][2] += k4.z * v4.z; acc[r + 2][3] += k4.z * v4.w;
                    acc[r + 3][0] += k4.w * v4.x; acc[r + 3][1] += k4.w * v4.y; acc[r + 3][2] += k4.w * v4.z; acc[r + 3][3] += k4.w * v4.w;
                }
            }
#pragma unroll
            for (int i = 0; i < 16; i++) {
                float4 w = *(float4*)&Wt[(kk0 + i) * 64 + dv0];
                w.x = w.x * gC + acc[i][0]; w.y = w.y * gC + acc[i][1];
                w.z = w.z * gC + acc[i][2]; w.w = w.w * gC + acc[i][3];
                *(float4*)&Wt[(kk0 + i) * 64 + dv0] = w;
            }
        }
        __syncthreads();
    }
}

// ---------------- host launcher ----------------
extern "C" void kernel_launch(void* const* d_in, const int* in_sizes, int n_in,
                              void* d_out, int out_size)
{
    (void)in_sizes; (void)n_in; (void)out_size;
    const float* x       = (const float*)d_in[0];
    const float* norm_w  = (const float*)d_in[1];
    const float* proj_w  = (const float*)d_in[2];
    const float* gate_w  = (const float*)d_in[3];
    const float* conv_w  = (const float*)d_in[4];
    const float* conv_b  = (const float*)d_in[5];
    const float* outpw   = (const float*)d_in[6];
    const float* write_w = (const float*)d_in[7];
    const float* read_w  = (const float*)d_in[8];
    const float* decay   = (const float*)d_in[9];
    const float* lalpha  = (const float*)d_in[10];
    float* outO = (float*)d_out;

    float *h, *val, *u, *o, *v, *intra, *interp;
    cudaGetSymbolAddress((void**)&h, g_h);
    cudaGetSymbolAddress((void**)&val, g_val);
    cudaGetSymbolAddress((void**)&u, g_u);
    cudaGetSymbolAddress((void**)&o, g_out);
    cudaGetSymbolAddress((void**)&v, g_v);
    cudaGetSymbolAddress((void**)&intra, g_intra);
    cudaGetSymbolAddress((void**)&interp, g_interp);

    const float* nul = nullptr;
    const size_t SZ = (size_t)MROWS * DDIM;

    rmsnorm_kernel<<<MROWS, 256>>>(x, norm_w, h);

    gemm_nt<0><<<dim3(EDIM / 128, MROWS / 128), 256>>>(h, proj_w, val, EDIM, DDIM,
                                                       nul, nul, nul, nul, nul, nul);
    gemm_nt<1><<<dim3(EDIM / 128, MROWS / 128), 256>>>(h, gate_w, u, EDIM, DDIM,
                                                       val, conv_w, conv_b, nul, nul, nul);
    gemm_nt<0><<<dim3(DDIM / 128, MROWS / 128), 256>>>(u, outpw, o, DDIM, EDIM,
                                                       nul, nul, nul, nul, nul, nul);
    gemm_nt<0><<<dim3(DDIM / 128, MROWS / 128), 256>>>(o, write_w, v, DDIM, DDIM,
                                                       nul, nul, nul, nul, nul, nul);

    intra_kernel<<<dim3(TDIM / 64, BDIM), 256>>>(o, v, intra, decay);

    const int scan_smem = SCAN_SMEM_FLOATS * 4;
    cudaFuncSetAttribute(scan_kernel, cudaFuncAttributeMaxDynamicSharedMemorySize, scan_smem);
    scan_kernel<<<dim3(3, DDIM / 64, BDIM), 256, scan_smem>>>(o, v, interp, decay);

    gemm_nt<2><<<dim3(DDIM / 128, MROWS / 128), 256>>>(intra, read_w, outO, DDIM, DDIM,
                                                       interp, interp + SZ, interp + 2 * SZ,
                                                       x, o, lalpha);
}

// round 9
// speedup vs baseline: 1.6727x; 1.6727x over previous
#include <cuda_runtime.h>
#include <cuda_bf16.h>
#include <math.h>
#include <stdint.h>

#define TDIM 4096
#define DDIM 768
#define EDIM 1536
#define BDIM 8
#define MROWS (BDIM * TDIM)

__device__ float g_h[(size_t)MROWS * DDIM];
__device__ float g_val[(size_t)MROWS * EDIM];
__device__ float g_gs[(size_t)MROWS * EDIM];
__device__ float g_u[(size_t)MROWS * EDIM];
__device__ float g_out[(size_t)MROWS * DDIM];
__device__ float g_v[(size_t)MROWS * DDIM];
__device__ float g_intra[(size_t)MROWS * DDIM];
__device__ float g_interp[3 * (size_t)MROWS * DDIM];

// ================= helpers =================
__device__ __forceinline__ uint32_t smem_u32(const void* p) {
    uint32_t a;
    asm("{ .reg .u64 t; cvta.to.shared.u64 t, %1; cvt.u32.u64 %0, t; }" : "=r"(a) : "l"(p));
    return a;
}
__device__ __forceinline__ void ldsm4(uint32_t* r, uint32_t addr) {
    asm volatile("ldmatrix.sync.aligned.m8n8.x4.shared.b16 {%0,%1,%2,%3}, [%4];"
        : "=r"(r[0]), "=r"(r[1]), "=r"(r[2]), "=r"(r[3]) : "r"(addr));
}
__device__ __forceinline__ void mma16816(float* c, const uint32_t* a, const uint32_t* b) {
    asm volatile("mma.sync.aligned.m16n8k16.row.col.f32.bf16.bf16.f32 "
        "{%0,%1,%2,%3}, {%4,%5,%6,%7}, {%8,%9}, {%0,%1,%2,%3};"
        : "+f"(c[0]), "+f"(c[1]), "+f"(c[2]), "+f"(c[3])
        : "r"(a[0]), "r"(a[1]), "r"(a[2]), "r"(a[3]), "r"(b[0]), "r"(b[1]));
}
__device__ __forceinline__ void split2(float a, float b, uint32_t& hi, uint32_t& lo) {
    __nv_bfloat16 ha = __float2bfloat16(a), hb = __float2bfloat16(b);
    float ra = a - __bfloat162float(ha), rb = b - __bfloat162float(hb);
    __nv_bfloat162 hp, lp;
    hp.x = ha; hp.y = hb;
    lp.x = __float2bfloat16(ra); lp.y = __float2bfloat16(rb);
    hi = *(uint32_t*)&hp; lo = *(uint32_t*)&lp;
}

// ================= rmsnorm =================
__global__ void __launch_bounds__(256) rmsnorm_kernel(const float* __restrict__ x,
                                                      const float* __restrict__ w,
                                                      float* __restrict__ h)
{
    const int m = blockIdx.x;
    const float* row = x + (size_t)m * DDIM;
    float s = 0.f;
#pragma unroll
    for (int i = 0; i < 3; i++) { float v = row[threadIdx.x + i * 256]; s += v * v; }
#pragma unroll
    for (int o = 16; o; o >>= 1) s += __shfl_xor_sync(0xffffffffu, s, o);
    __shared__ float red[8];
    if ((threadIdx.x & 31) == 0) red[threadIdx.x >> 5] = s;
    __syncthreads();
    float tot = 0.f;
#pragma unroll
    for (int i = 0; i < 8; i++) tot += red[i];
    const float rs = rsqrtf(tot / (float)DDIM + 1e-5f);
    float* hrow = h + (size_t)m * DDIM;
#pragma unroll
    for (int i = 0; i < 3; i++) {
        int idx = threadIdx.x + i * 256;
        hrow[idx] = row[idx] * rs * w[idx];
    }
}

// ======== HMMA NT GEMM: C[M,N] = A[M,K] @ B[N,K]^T, bf16x3 split ========
// 128x128 CTA tile, kc=32 stages, double-buffered. 8 warps of 64x32.
// MODE 0: C=acc. MODE 1: C=silu(acc). MODE 2: A = A+P0+P1+P2; C = X+O+exp(*LA)*acc.
#define RSB 80                       // smem row stride bytes (40 bf16)
#define OFF_AH 0
#define OFF_AL (128 * RSB)
#define OFF_BH (2 * 128 * RSB)
#define OFF_BL (3 * 128 * RSB)
#define STAGE  (4 * 128 * RSB)       // 40960 B
#define MMA_SMEM (2 * STAGE)         // 81920 B

template <int MODE>
__global__ void __launch_bounds__(256, 1) mma_gemm(
    const float* __restrict__ A, const float* __restrict__ Bw, float* __restrict__ C,
    int N, int K,
    const float* __restrict__ P0, const float* __restrict__ P1, const float* __restrict__ P2,
    const float* __restrict__ X, const float* __restrict__ O, const float* __restrict__ LA)
{
    extern __shared__ char sm[];
    const uint32_t sb = smem_u32(sm);
    const int tid = threadIdx.x, wid = tid >> 5, lane = tid & 31;
    const int bm = blockIdx.y * 128, bn = blockIdx.x * 128;
    const int wm = (wid & 1) * 64, wn = (wid >> 1) * 32;
    const int NS = K >> 5;

    float c[4][4][4];
#pragma unroll
    for (int i = 0; i < 4; i++)
#pragma unroll
        for (int j = 0; j < 4; j++)
#pragma unroll
            for (int q = 0; q < 4; q++) c[i][j][q] = 0.f;

    // per-lane ldmatrix base offsets (bytes, relative to tile start)
    const int g = lane >> 3, lr = lane & 7;
    const uint32_t abase = (uint32_t)((wm + (g & 1) * 8 + lr) * RSB + (g >> 1) * 16);
    const uint32_t bbase = (uint32_t)((wn + (g >> 1) * 8 + lr) * RSB + (g & 1) * 16);

    float4 ra[4], rb[4];
    auto fetch = [&](int ck) {
#pragma unroll
        for (int i = 0; i < 4; i++) {
            int f4 = i * 256 + tid;
            int row = f4 >> 3, colq = (f4 & 7) << 2;
            size_t off = (size_t)(bm + row) * K + (size_t)ck * 32 + colq;
            float4 v = *(const float4*)(A + off);
            if (MODE == 2) {
                float4 a1 = *(const float4*)(P0 + off);
                float4 a2 = *(const float4*)(P1 + off);
                float4 a3 = *(const float4*)(P2 + off);
                v.x += a1.x + a2.x + a3.x; v.y += a1.y + a2.y + a3.y;
                v.z += a1.z + a2.z + a3.z; v.w += a1.w + a2.w + a3.w;
            }
            ra[i] = v;
            rb[i] = *(const float4*)(Bw + (size_t)(bn + row) * K + (size_t)ck * 32 + colq);
        }
    };
    auto stor = [&](int buf) {
        char* tb = sm + buf * STAGE;
#pragma unroll
        for (int i = 0; i < 4; i++) {
            int f4 = i * 256 + tid;
            int row = f4 >> 3, colq = (f4 & 7) << 2;
            int ba = row * RSB + colq * 2;
            uint2 hi, lo;
            split2(ra[i].x, ra[i].y, hi.x, lo.x);
            split2(ra[i].z, ra[i].w, hi.y, lo.y);
            *(uint2*)(tb + OFF_AH + ba) = hi;
            *(uint2*)(tb + OFF_AL + ba) = lo;
            split2(rb[i].x, rb[i].y, hi.x, lo.x);
            split2(rb[i].z, rb[i].w, hi.y, lo.y);
            *(uint2*)(tb + OFF_BH + ba) = hi;
            *(uint2*)(tb + OFF_BL + ba) = lo;
        }
    };

    fetch(0); stor(0); __syncthreads();

    for (int ck = 0; ck < NS; ck++) {
        const int buf = ck & 1;
        if (ck + 1 < NS) fetch(ck + 1);
        const uint32_t tb = sb + buf * STAGE;
#pragma unroll
        for (int ks = 0; ks < 2; ks++) {
            const uint32_t koff = ks * 32;   // 16 bf16 cols = 32 bytes
            uint32_t a[4][4], b[2][4];
            // pass 1: Ah * Bh
#pragma unroll
            for (int mi = 0; mi < 4; mi++)
                ldsm4(a[mi], tb + OFF_AH + abase + mi * (16 * RSB) + koff);
#pragma unroll
            for (int nt = 0; nt < 2; nt++)
                ldsm4(b[nt], tb + OFF_BH + bbase + nt * (16 * RSB) + koff);
#pragma unroll
            for (int mi = 0; mi < 4; mi++)
#pragma unroll
                for (int ni = 0; ni < 4; ni++)
                    mma16816(c[mi][ni], a[mi], &b[ni >> 1][(ni & 1) * 2]);
            // pass 2: Ah * Bl
#pragma unroll
            for (int nt = 0; nt < 2; nt++)
                ldsm4(b[nt], tb + OFF_BL + bbase + nt * (16 * RSB) + koff);
#pragma unroll
            for (int mi = 0; mi < 4; mi++)
#pragma unroll
                for (int ni = 0; ni < 4; ni++)
                    mma16816(c[mi][ni], a[mi], &b[ni >> 1][(ni & 1) * 2]);
            // pass 3: Al * Bh
#pragma unroll
            for (int mi = 0; mi < 4; mi++)
                ldsm4(a[mi], tb + OFF_AL + abase + mi * (16 * RSB) + koff);
#pragma unroll
            for (int nt = 0; nt < 2; nt++)
                ldsm4(b[nt], tb + OFF_BH + bbase + nt * (16 * RSB) + koff);
#pragma unroll
            for (int mi = 0; mi < 4; mi++)
#pragma unroll
                for (int ni = 0; ni < 4; ni++)
                    mma16816(c[mi][ni], a[mi], &b[ni >> 1][(ni & 1) * 2]);
        }
        if (ck + 1 < NS) stor(buf ^ 1);
        __syncthreads();
    }

    // -------- epilogue: direct fragment stores --------
    float alpha = 0.f;
    if (MODE == 2) alpha = expf(LA[0]);
    const int er = lane >> 2, ec = (lane & 3) * 2;
#pragma unroll
    for (int mi = 0; mi < 4; mi++) {
#pragma unroll
        for (int ni = 0; ni < 4; ni++) {
            int m0 = bm + wm + mi * 16 + er;
            int n0 = bn + wn + ni * 8 + ec;
#pragma unroll
            for (int half = 0; half < 2; half++) {
                int m = m0 + half * 8;
                size_t idx = (size_t)m * N + n0;
                float r0 = c[mi][ni][half * 2], r1 = c[mi][ni][half * 2 + 1];
                float2 o;
                if (MODE == 0) { o.x = r0; o.y = r1; }
                else if (MODE == 1) {
                    o.x = r0 / (1.f + expf(-r0));
                    o.y = r1 / (1.f + expf(-r1));
                } else {
                    o.x = X[idx] + O[idx] + alpha * r0;
                    o.y = X[idx + 1] + O[idx + 1] + alpha * r1;
                }
                *(float2*)(C + idx) = o;
            }
        }
    }
}

// ========== causal depthwise conv + silu gate combine ==========
__global__ void __launch_bounds__(256) conv_kernel(const float* __restrict__ val,
                                                   const float* __restrict__ gs,
                                                   const float* __restrict__ cw,
                                                   const float* __restrict__ cb,
                                                   float* __restrict__ u)
{
    const int e = blockIdx.x * 256 + threadIdx.x;
    const int r0 = blockIdx.y * 64;
    const int t0 = r0 & (TDIM - 1);
    const float w0 = cw[e * 4], w1 = cw[e * 4 + 1], w2 = cw[e * 4 + 2], w3 = cw[e * 4 + 3];
    const float bb = cb[e];
    float p1 = 0.f, p2 = 0.f, p3 = 0.f;
    if (t0 > 0) {
        p1 = val[(size_t)(r0 - 1) * EDIM + e];
        p2 = val[(size_t)(r0 - 2) * EDIM + e];
        p3 = val[(size_t)(r0 - 3) * EDIM + e];
    }
#pragma unroll 4
    for (int i = 0; i < 64; i++) {
        size_t idx = (size_t)(r0 + i) * EDIM + e;
        float v = val[idx];
        float cc = bb + w0 * p3 + w1 * p2 + w2 * p1 + w3 * v;
        float s = cc / (1.f + expf(-cc));
        u[idx] = s * gs[idx];
        p3 = p2; p2 = p1; p1 = v;
    }
}

// -------- chunk-local: S = r k^T (k shifted), intra = (S .* M) v --------
__global__ void __launch_bounds__(256) intra_kernel(const float* __restrict__ outp,
                                                    const float* __restrict__ vp,
                                                    float* __restrict__ intrap,
                                                    const float* __restrict__ decayp)
{
    __shared__ float Rt[16][68];
    __shared__ float Kt[16][68];
    __shared__ float SMt[64][68];
    __shared__ float Vs[64][68];

    const int ch = blockIdx.x, b = blockIdx.y;
    const int t0 = ch * 64;
    const int tid = threadIdx.x;
    const int tx = tid & 15, ty = tid >> 4;
    const int lc = tid >> 2, lq = tid & 3;
    const float gamma = 1.f / (1.f + expf(-decayp[0]));
    const float lg = logf(gamma);

    const float* outB = outp + (size_t)b * TDIM * DDIM;
    const float* vB = vp + (size_t)b * TDIM * DDIM;

    const int c0 = ty * 4, e0 = tx * 4;
    float acc[4][4];
#pragma unroll
    for (int i = 0; i < 4; i++)
#pragma unroll
        for (int j = 0; j < 4; j++) acc[i][j] = 0.f;

    for (int ks = 0; ks < DDIM / 16; ks++) {
        {
            float4 r4 = *(const float4*)(outB + (size_t)(t0 + lc) * DDIM + ks * 16 + lq * 4);
            Rt[lq * 4 + 0][lc] = r4.x; Rt[lq * 4 + 1][lc] = r4.y;
            Rt[lq * 4 + 2][lc] = r4.z; Rt[lq * 4 + 3][lc] = r4.w;
            int tk = t0 + lc - 1;
            float4 k4 = make_float4(0.f, 0.f, 0.f, 0.f);
            if (tk >= 0) k4 = *(const float4*)(outB + (size_t)tk * DDIM + ks * 16 + lq * 4);
            Kt[lq * 4 + 0][lc] = k4.x; Kt[lq * 4 + 1][lc] = k4.y;
            Kt[lq * 4 + 2][lc] = k4.z; Kt[lq * 4 + 3][lc] = k4.w;
        }
        __syncthreads();
#pragma unroll
        for (int k = 0; k < 16; k++) {
            float4 a = *(const float4*)&Rt[k][c0];
            float4 bb = *(const float4*)&Kt[k][e0];
            acc[0][0] += a.x * bb.x; acc[0][1] += a.x * bb.y; acc[0][2] += a.x * bb.z; acc[0][3] += a.x * bb.w;
            acc[1][0] += a.y * bb.x; acc[1][1] += a.y * bb.y; acc[1][2] += a.y * bb.z; acc[1][3] += a.y * bb.w;
            acc[2][0] += a.z * bb.x; acc[2][1] += a.z * bb.y; acc[2][2] += a.z * bb.z; acc[2][3] += a.z * bb.w;
            acc[3][0] += a.w * bb.x; acc[3][1] += a.w * bb.y; acc[3][2] += a.w * bb.z; acc[3][3] += a.w * bb.w;
        }
        __syncthreads();
    }
#pragma unroll
    for (int i = 0; i < 4; i++)
#pragma unroll
        for (int j = 0; j < 4; j++) {
            int c = c0 + i, e = e0 + j;
            float mval = (c > e) ? expf(lg * (float)(c - 1 - e)) : 0.f;
            SMt[e][c] = acc[i][j] * mval;
        }
    __syncthreads();

    for (int db = 0; db < DDIM / 64; db++) {
#pragma unroll
        for (int i = 0; i < 4; i++)
            *(float4*)&Vs[lc][lq * 16 + i * 4] =
                *(const float4*)(vB + (size_t)(t0 + lc) * DDIM + db * 64 + lq * 16 + i * 4);
        __syncthreads();
        float a2[4][4];
#pragma unroll
        for (int i = 0; i < 4; i++)
#pragma unroll
            for (int j = 0; j < 4; j++) a2[i][j] = 0.f;
#pragma unroll 8
        for (int e = 0; e < 64; e++) {
            float4 a = *(const float4*)&SMt[e][c0];
            float4 bb = *(const float4*)&Vs[e][tx * 4];
            a2[0][0] += a.x * bb.x; a2[0][1] += a.x * bb.y; a2[0][2] += a.x * bb.z; a2[0][3] += a.x * bb.w;
            a2[1][0] += a.y * bb.x; a2[1][1] += a.y * bb.y; a2[1][2] += a.y * bb.z; a2[1][3] += a.y * bb.w;
            a2[2][0] += a.z * bb.x; a2[2][1] += a.z * bb.y; a2[2][2] += a.z * bb.z; a2[2][3] += a.z * bb.w;
            a2[3][0] += a.w * bb.x; a2[3][1] += a.w * bb.y; a2[3][2] += a.w * bb.z; a2[3][3] += a.w * bb.w;
        }
#pragma unroll
        for (int i = 0; i < 4; i++)
            *(float4*)(intrap + (size_t)b * TDIM * DDIM + (size_t)(t0 + c0 + i) * DDIM + db * 64 + tx * 4)
                = make_float4(a2[i][0], a2[i][1], a2[i][2], a2[i][3]);
        __syncthreads();
    }
}

// -------- recurrent scan: W tile [kk 256][dv 64] per CTA --------
#define SCAN_SMEM_FLOATS (256 * 64 + 256 * 68 + 64 * 260 + 64 * 68)

__global__ void __launch_bounds__(256) scan_kernel(const float* __restrict__ outp,
                                                   const float* __restrict__ vp,
                                                   float* __restrict__ interp,
                                                   const float* __restrict__ decayp)
{
    extern __shared__ float smf[];
    float* Wt = smf;
    float* Rt = Wt + 256 * 64;
    float* Ks = Rt + 256 * 68;
    float* Vg = Ks + 64 * 260;

    const int slab = blockIdx.x, dvb = blockIdx.y, b = blockIdx.z;
    const int kkbase = slab * 256, dvbase = dvb * 64;
    const int tid = threadIdx.x;
    const float gamma = 1.f / (1.f + expf(-decayp[0]));
    const float lg = logf(gamma);
    const float gC = expf(lg * 64.f);

    for (int i = tid; i < 256 * 64; i += 256) Wt[i] = 0.f;

    const float* outB = outp + (size_t)b * TDIM * DDIM;
    const float* vB = vp + (size_t)b * TDIM * DDIM;
    float* ipB = interp + (size_t)slab * ((size_t)MROWS * DDIM) + (size_t)b * TDIM * DDIM;

    const int tx = tid & 15, ty = tid >> 4;
    const int lc = tid >> 2, lq = tid & 3;
    const float gwc = expf(lg * (float)(63 - lc));
    __syncthreads();

    for (int ch = 0; ch < 64; ch++) {
        const int t0 = ch * 64;
        {
            const float* rrow = outB + (size_t)(t0 + lc) * DDIM + kkbase + lq * 64;
#pragma unroll
            for (int i = 0; i < 16; i++) {
                float4 v4 = *(const float4*)(rrow + i * 4);
                int kk = lq * 64 + i * 4;
                Rt[(kk + 0) * 68 + lc] = v4.x; Rt[(kk + 1) * 68 + lc] = v4.y;
                Rt[(kk + 2) * 68 + lc] = v4.z; Rt[(kk + 3) * 68 + lc] = v4.w;
            }
            int tk = t0 + lc - 1;
            if (tk >= 0) {
                const float* krow = outB + (size_t)tk * DDIM + kkbase + lq * 64;
#pragma unroll
                for (int i = 0; i < 16; i++)
                    *(float4*)&Ks[lc * 260 + lq * 64 + i * 4] = *(const float4*)(krow + i * 4);
            } else {
                float4 z = make_float4(0.f, 0.f, 0.f, 0.f);
#pragma unroll
                for (int i = 0; i < 16; i++)
                    *(float4*)&Ks[lc * 260 + lq * 64 + i * 4] = z;
            }
            const float* vrow = vB + (size_t)(t0 + lc) * DDIM + dvbase + lq * 16;
#pragma unroll
            for (int i = 0; i < 4; i++) {
                float4 v4 = *(const float4*)(vrow + i * 4);
                v4.x *= gwc; v4.y *= gwc; v4.z *= gwc; v4.w *= gwc;
                *(float4*)&Vg[lc * 68 + lq * 16 + i * 4] = v4;
            }
        }
        __syncthreads();
        {
            const int c0 = ty * 4, dv0 = tx * 4;
            float acc[4][4];
#pragma unroll
            for (int i = 0; i < 4; i++)
#pragma unroll
                for (int j = 0; j < 4; j++) acc[i][j] = 0.f;
#pragma unroll 4
            for (int k = 0; k < 256; k++) {
                float4 a = *(const float4*)&Rt[k * 68 + c0];
                float4 w = *(const float4*)&Wt[k * 64 + dv0];
                acc[0][0] += a.x * w.x; acc[0][1] += a.x * w.y; acc[0][2] += a.x * w.z; acc[0][3] += a.x * w.w;
                acc[1][0] += a.y * w.x; acc[1][1] += a.y * w.y; acc[1][2] += a.y * w.z; acc[1][3] += a.y * w.w;
                acc[2][0] += a.z * w.x; acc[2][1] += a.z * w.y; acc[2][2] += a.z * w.z; acc[2][3] += a.z * w.w;
                acc[3][0] += a.w * w.x; acc[3][1] += a.w * w.y; acc[3][2] += a.w * w.z; acc[3][3] += a.w * w.w;
            }
#pragma unroll
            for (int i = 0; i < 4; i++) {
                float gpc = expf(lg * (float)(c0 + i));
                *(float4*)(ipB + (size_t)(t0 + c0 + i) * DDIM + dvbase + dv0) =
                    make_float4(acc[i][0] * gpc, acc[i][1] * gpc, acc[i][2] * gpc, acc[i][3] * gpc);
            }
        }
        __syncthreads();
        {
            const int dv0 = tx * 4, kk0 = ty * 16;
            float acc[16][4];
#pragma unroll
            for (int i = 0; i < 16; i++)
#pragma unroll
                for (int j = 0; j < 4; j++) acc[i][j] = 0.f;
#pragma unroll 4
            for (int cc = 0; cc < 64; cc++) {
                float4 v4 = *(const float4*)&Vg[cc * 68 + dv0];
#pragma unroll
                for (int ii = 0; ii < 4; ii++) {
                    float4 k4 = *(const float4*)&Ks[cc * 260 + kk0 + ii * 4];
                    int r = ii * 4;
                    acc[r + 0][0] += k4.x * v4.x; acc[r + 0][1] += k4.x * v4.y; acc[r + 0][2] += k4.x * v4.z; acc[r + 0][3] += k4.x * v4.w;
                    acc[r + 1][0] += k4.y * v4.x; acc[r + 1][1] += k4.y * v4.y; acc[r + 1][2] += k4.y * v4.z; acc[r + 1][3] += k4.y * v4.w;
                    acc[r + 2][0] += k4.z * v4.x; acc[r + 2][1] += k4.z * v4.y; acc[r + 2][2] += k4.z * v4.z; acc[r + 2][3] += k4.z * v4.w;
                    acc[r + 3][0] += k4.w * v4.x; acc[r + 3][1] += k4.w * v4.y; acc[r + 3][2] += k4.w * v4.z; acc[r + 3][3] += k4.w * v4.w;
                }
            }
#pragma unroll
            for (int i = 0; i < 16; i++) {
                float4 w = *(float4*)&Wt[(kk0 + i) * 64 + dv0];
                w.x = w.x * gC + acc[i][0]; w.y = w.y * gC + acc[i][1];
                w.z = w.z * gC + acc[i][2]; w.w = w.w * gC + acc[i][3];
                *(float4*)&Wt[(kk0 + i) * 64 + dv0] = w;
            }
        }
        __syncthreads();
    }
}

// ================= host launcher =================
extern "C" void kernel_launch(void* const* d_in, const int* in_sizes, int n_in,
                              void* d_out, int out_size)
{
    (void)in_sizes; (void)n_in; (void)out_size;
    const float* x       = (const float*)d_in[0];
    const float* norm_w  = (const float*)d_in[1];
    const float* proj_w  = (const float*)d_in[2];
    const float* gate_w  = (const float*)d_in[3];
    const float* conv_w  = (const float*)d_in[4];
    const float* conv_b  = (const float*)d_in[5];
    const float* outpw   = (const float*)d_in[6];
    const float* write_w = (const float*)d_in[7];
    const float* read_w  = (const float*)d_in[8];
    const float* decay   = (const float*)d_in[9];
    const float* lalpha  = (const float*)d_in[10];
    float* outO = (float*)d_out;

    float *h, *val, *gs, *u, *o, *v, *intra, *interp;
    cudaGetSymbolAddress((void**)&h, g_h);
    cudaGetSymbolAddress((void**)&val, g_val);
    cudaGetSymbolAddress((void**)&gs, g_gs);
    cudaGetSymbolAddress((void**)&u, g_u);
    cudaGetSymbolAddress((void**)&o, g_out);
    cudaGetSymbolAddress((void**)&v, g_v);
    cudaGetSymbolAddress((void**)&intra, g_intra);
    cudaGetSymbolAddress((void**)&interp, g_interp);

    const float* nul = nullptr;
    const size_t SZ = (size_t)MROWS * DDIM;

    cudaFuncSetAttribute(mma_gemm<0>, cudaFuncAttributeMaxDynamicSharedMemorySize, MMA_SMEM);
    cudaFuncSetAttribute(mma_gemm<1>, cudaFuncAttributeMaxDynamicSharedMemorySize, MMA_SMEM);
    cudaFuncSetAttribute(mma_gemm<2>, cudaFuncAttributeMaxDynamicSharedMemorySize, MMA_SMEM);

    rmsnorm_kernel<<<MROWS, 256>>>(x, norm_w, h);

    // val = h @ proj_w^T
    mma_gemm<0><<<dim3(EDIM / 128, MROWS / 128), 256, MMA_SMEM>>>(
        h, proj_w, val, EDIM, DDIM, nul, nul, nul, nul, nul, nul);
    // gs = silu(h @ gate_w^T)
    mma_gemm<1><<<dim3(EDIM / 128, MROWS / 128), 256, MMA_SMEM>>>(
        h, gate_w, gs, EDIM, DDIM, nul, nul, nul, nul, nul, nul);
    // u = silu(conv(val)) * gs
    conv_kernel<<<dim3(EDIM / 256, MROWS / 64), 256>>>(val, gs, conv_w, conv_b, u);
    // o = u @ out_proj_w^T
    mma_gemm<0><<<dim3(DDIM / 128, MROWS / 128), 256, MMA_SMEM>>>(
        u, outpw, o, DDIM, EDIM, nul, nul, nul, nul, nul, nul);
    // v = o @ write_w^T
    mma_gemm<0><<<dim3(DDIM / 128, MROWS / 128), 256, MMA_SMEM>>>(
        o, write_w, v, DDIM, DDIM, nul, nul, nul, nul, nul, nul);

    intra_kernel<<<dim3(TDIM / 64, BDIM), 256>>>(o, v, intra, decay);

    const int scan_smem = SCAN_SMEM_FLOATS * 4;
    cudaFuncSetAttribute(scan_kernel, cudaFuncAttributeMaxDynamicSharedMemorySize, scan_smem);
    scan_kernel<<<dim3(3, DDIM / 64, BDIM), 256, scan_smem>>>(o, v, interp, decay);

    // out = x + o + exp(la) * ((intra + i0 + i1 + i2) @ read_w^T)
    mma_gemm<2><<<dim3(DDIM / 128, MROWS / 128), 256, MMA_SMEM>>>(
        intra, read_w, outO, DDIM, DDIM,
        interp, interp + SZ, interp + 2 * SZ, x, o, lalpha);
}

// round 10
// speedup vs baseline: 1.6730x; 1.0002x over previous
#include <cuda_runtime.h>
#include <cuda_bf16.h>
#include <math.h>
#include <stdint.h>

#define TDIM 4096
#define DDIM 768
#define EDIM 1536
#define BDIM 8
#define MROWS (BDIM * TDIM)

__device__ float g_h[(size_t)MROWS * DDIM];
__device__ float g_val[(size_t)MROWS * EDIM];
__device__ float g_gs[(size_t)MROWS * EDIM];
__device__ float g_u[(size_t)MROWS * EDIM];
__device__ float g_out[(size_t)MROWS * DDIM];
__device__ float g_v[(size_t)MROWS * DDIM];
__device__ float g_intra[(size_t)MROWS * DDIM];
__device__ float g_interp[3 * (size_t)MROWS * DDIM];

// ================= helpers =================
__device__ __forceinline__ uint32_t smem_u32(const void* p) {
    uint32_t a;
    asm("{ .reg .u64 t; cvta.to.shared.u64 t, %1; cvt.u32.u64 %0, t; }" : "=r"(a) : "l"(p));
    return a;
}
__device__ __forceinline__ void ldsm4(uint32_t* r, uint32_t addr) {
    asm volatile("ldmatrix.sync.aligned.m8n8.x4.shared.b16 {%0,%1,%2,%3}, [%4];"
        : "=r"(r[0]), "=r"(r[1]), "=r"(r[2]), "=r"(r[3]) : "r"(addr));
}
__device__ __forceinline__ void mma16816(float* c, const uint32_t* a, const uint32_t* b) {
    asm volatile("mma.sync.aligned.m16n8k16.row.col.f32.bf16.bf16.f32 "
        "{%0,%1,%2,%3}, {%4,%5,%6,%7}, {%8,%9}, {%0,%1,%2,%3};"
        : "+f"(c[0]), "+f"(c[1]), "+f"(c[2]), "+f"(c[3])
        : "r"(a[0]), "r"(a[1]), "r"(a[2]), "r"(a[3]), "r"(b[0]), "r"(b[1]));
}
__device__ __forceinline__ void split2(float a, float b, uint32_t& hi, uint32_t& lo) {
    __nv_bfloat16 ha = __float2bfloat16(a), hb = __float2bfloat16(b);
    float ra = a - __bfloat162float(ha), rb = b - __bfloat162float(hb);
    __nv_bfloat162 hp, lp;
    hp.x = ha; hp.y = hb;
    lp.x = __float2bfloat16(ra); lp.y = __float2bfloat16(rb);
    hi = *(uint32_t*)&hp; lo = *(uint32_t*)&lp;
}

// ================= rmsnorm =================
__global__ void __launch_bounds__(256) rmsnorm_kernel(const float* __restrict__ x,
                                                      const float* __restrict__ w,
                                                      float* __restrict__ h)
{
    const int m = blockIdx.x;
    const float* row = x + (size_t)m * DDIM;
    float s = 0.f;
#pragma unroll
    for (int i = 0; i < 3; i++) { float v = row[threadIdx.x + i * 256]; s += v * v; }
#pragma unroll
    for (int o = 16; o; o >>= 1) s += __shfl_xor_sync(0xffffffffu, s, o);
    __shared__ float red[8];
    if ((threadIdx.x & 31) == 0) red[threadIdx.x >> 5] = s;
    __syncthreads();
    float tot = 0.f;
#pragma unroll
    for (int i = 0; i < 8; i++) tot += red[i];
    const float rs = rsqrtf(tot / (float)DDIM + 1e-5f);
    float* hrow = h + (size_t)m * DDIM;
#pragma unroll
    for (int i = 0; i < 3; i++) {
        int idx = threadIdx.x + i * 256;
        hrow[idx] = row[idx] * rs * w[idx];
    }
}

// ======== HMMA NT GEMM: C[M,N] = A[M,K] @ B[N,K]^T, bf16x3 split ========
// 128x128 CTA tile, kc=32 stages, double-buffered. 8 warps of 64x32.
// MODE 0: C=acc. MODE 1: C=silu(acc). MODE 2: A = A+P0+P1+P2; C = X+O+exp(*LA)*acc.
#define RSB 80                       // smem row stride bytes (40 bf16)
#define OFF_AH 0
#define OFF_AL (128 * RSB)
#define OFF_BH (2 * 128 * RSB)
#define OFF_BL (3 * 128 * RSB)
#define STAGE  (4 * 128 * RSB)       // 40960 B
#define MMA_SMEM (2 * STAGE)         // 81920 B

template <int MODE>
__global__ void __launch_bounds__(256, 1) mma_gemm(
    const float* __restrict__ A, const float* __restrict__ Bw, float* __restrict__ C,
    int N, int K,
    const float* __restrict__ P0, const float* __restrict__ P1, const float* __restrict__ P2,
    const float* __restrict__ X, const float* __restrict__ O, const float* __restrict__ LA)
{
    extern __shared__ char sm[];
    const uint32_t sb = smem_u32(sm);
    const int tid = threadIdx.x, wid = tid >> 5, lane = tid & 31;
    const int bm = blockIdx.y * 128, bn = blockIdx.x * 128;
    const int wm = (wid & 1) * 64, wn = (wid >> 1) * 32;
    const int NS = K >> 5;

    float c[4][4][4];
#pragma unroll
    for (int i = 0; i < 4; i++)
#pragma unroll
        for (int j = 0; j < 4; j++)
#pragma unroll
            for (int q = 0; q < 4; q++) c[i][j][q] = 0.f;

    // per-lane ldmatrix base offsets (bytes, relative to tile start)
    const int g = lane >> 3, lr = lane & 7;
    const uint32_t abase = (uint32_t)((wm + (g & 1) * 8 + lr) * RSB + (g >> 1) * 16);
    const uint32_t bbase = (uint32_t)((wn + (g >> 1) * 8 + lr) * RSB + (g & 1) * 16);

    float4 ra[4], rb[4];
    auto fetch = [&](int ck) {
#pragma unroll
        for (int i = 0; i < 4; i++) {
            int f4 = i * 256 + tid;
            int row = f4 >> 3, colq = (f4 & 7) << 2;
            size_t off = (size_t)(bm + row) * K + (size_t)ck * 32 + colq;
            float4 v = *(const float4*)(A + off);
            if (MODE == 2) {
                float4 a1 = *(const float4*)(P0 + off);
                float4 a2 = *(const float4*)(P1 + off);
                float4 a3 = *(const float4*)(P2 + off);
                v.x += a1.x + a2.x + a3.x; v.y += a1.y + a2.y + a3.y;
                v.z += a1.z + a2.z + a3.z; v.w += a1.w + a2.w + a3.w;
            }
            ra[i] = v;
            rb[i] = *(const float4*)(Bw + (size_t)(bn + row) * K + (size_t)ck * 32 + colq);
        }
    };
    auto stor = [&](int buf) {
        char* tb = sm + buf * STAGE;
#pragma unroll
        for (int i = 0; i < 4; i++) {
            int f4 = i * 256 + tid;
            int row = f4 >> 3, colq = (f4 & 7) << 2;
            int ba = row * RSB + colq * 2;
            uint2 hi, lo;
            split2(ra[i].x, ra[i].y, hi.x, lo.x);
            split2(ra[i].z, ra[i].w, hi.y, lo.y);
            *(uint2*)(tb + OFF_AH + ba) = hi;
            *(uint2*)(tb + OFF_AL + ba) = lo;
            split2(rb[i].x, rb[i].y, hi.x, lo.x);
            split2(rb[i].z, rb[i].w, hi.y, lo.y);
            *(uint2*)(tb + OFF_BH + ba) = hi;
            *(uint2*)(tb + OFF_BL + ba) = lo;
        }
    };

    fetch(0); stor(0); __syncthreads();

    for (int ck = 0; ck < NS; ck++) {
        const int buf = ck & 1;
        if (ck + 1 < NS) fetch(ck + 1);
        const uint32_t tb = sb + buf * STAGE;
#pragma unroll
        for (int ks = 0; ks < 2; ks++) {
            const uint32_t koff = ks * 32;   // 16 bf16 cols = 32 bytes
            uint32_t a[4][4], b[2][4];
            // pass 1: Ah * Bh
#pragma unroll
            for (int mi = 0; mi < 4; mi++)
                ldsm4(a[mi], tb + OFF_AH + abase + mi * (16 * RSB) + koff);
#pragma unroll
            for (int nt = 0; nt < 2; nt++)
                ldsm4(b[nt], tb + OFF_BH + bbase + nt * (16 * RSB) + koff);
#pragma unroll
            for (int mi = 0; mi < 4; mi++)
#pragma unroll
                for (int ni = 0; ni < 4; ni++)
                    mma16816(c[mi][ni], a[mi], &b[ni >> 1][(ni & 1) * 2]);
            // pass 2: Ah * Bl
#pragma unroll
            for (int nt = 0; nt < 2; nt++)
                ldsm4(b[nt], tb + OFF_BL + bbase + nt * (16 * RSB) + koff);
#pragma unroll
            for (int mi = 0; mi < 4; mi++)
#pragma unroll
                for (int ni = 0; ni < 4; ni++)
                    mma16816(c[mi][ni], a[mi], &b[ni >> 1][(ni & 1) * 2]);
            // pass 3: Al * Bh
#pragma unroll
            for (int mi = 0; mi < 4; mi++)
                ldsm4(a[mi], tb + OFF_AL + abase + mi * (16 * RSB) + koff);
#pragma unroll
            for (int nt = 0; nt < 2; nt++)
                ldsm4(b[nt], tb + OFF_BH + bbase + nt * (16 * RSB) + koff);
#pragma unroll
            for (int mi = 0; mi < 4; mi++)
#pragma unroll
                for (int ni = 0; ni < 4; ni++)
                    mma16816(c[mi][ni], a[mi], &b[ni >> 1][(ni & 1) * 2]);
        }
        if (ck + 1 < NS) stor(buf ^ 1);
        __syncthreads();
    }

    // -------- epilogue: direct fragment stores --------
    float alpha = 0.f;
    if (MODE == 2) alpha = expf(LA[0]);
    const int er = lane >> 2, ec = (lane & 3) * 2;
#pragma unroll
    for (int mi = 0; mi < 4; mi++) {
#pragma unroll
        for (int ni = 0; ni < 4; ni++) {
            int m0 = bm + wm + mi * 16 + er;
            int n0 = bn + wn + ni * 8 + ec;
#pragma unroll
            for (int half = 0; half < 2; half++) {
                int m = m0 + half * 8;
                size_t idx = (size_t)m * N + n0;
                float r0 = c[mi][ni][half * 2], r1 = c[mi][ni][half * 2 + 1];
                float2 o;
                if (MODE == 0) { o.x = r0; o.y = r1; }
                else if (MODE == 1) {
                    o.x = r0 / (1.f + expf(-r0));
                    o.y = r1 / (1.f + expf(-r1));
                } else {
                    o.x = X[idx] + O[idx] + alpha * r0;
                    o.y = X[idx + 1] + O[idx + 1] + alpha * r1;
                }
                *(float2*)(C + idx) = o;
            }
        }
    }
}

// ========== causal depthwise conv + silu gate combine ==========
__global__ void __launch_bounds__(256) conv_kernel(const float* __restrict__ val,
                                                   const float* __restrict__ gs,
                                                   const float* __restrict__ cw,
                                                   const float* __restrict__ cb,
                                                   float* __restrict__ u)
{
    const int e = blockIdx.x * 256 + threadIdx.x;
    const int r0 = blockIdx.y * 64;
    const int t0 = r0 & (TDIM - 1);
    const float w0 = cw[e * 4], w1 = cw[e * 4 + 1], w2 = cw[e * 4 + 2], w3 = cw[e * 4 + 3];
    const float bb = cb[e];
    float p1 = 0.f, p2 = 0.f, p3 = 0.f;
    if (t0 > 0) {
        p1 = val[(size_t)(r0 - 1) * EDIM + e];
        p2 = val[(size_t)(r0 - 2) * EDIM + e];
        p3 = val[(size_t)(r0 - 3) * EDIM + e];
    }
#pragma unroll 4
    for (int i = 0; i < 64; i++) {
        size_t idx = (size_t)(r0 + i) * EDIM + e;
        float v = val[idx];
        float cc = bb + w0 * p3 + w1 * p2 + w2 * p1 + w3 * v;
        float s = cc / (1.f + expf(-cc));
        u[idx] = s * gs[idx];
        p3 = p2; p2 = p1; p1 = v;
    }
}

// -------- chunk-local: S = r k^T (k shifted), intra = (S .* M) v --------
__global__ void __launch_bounds__(256) intra_kernel(const float* __restrict__ outp,
                                                    const float* __restrict__ vp,
                                                    float* __restrict__ intrap,
                                                    const float* __restrict__ decayp)
{
    __shared__ float Rt[16][68];
    __shared__ float Kt[16][68];
    __shared__ float SMt[64][68];
    __shared__ float Vs[64][68];

    const int ch = blockIdx.x, b = blockIdx.y;
    const int t0 = ch * 64;
    const int tid = threadIdx.x;
    const int tx = tid & 15, ty = tid >> 4;
    const int lc = tid >> 2, lq = tid & 3;
    const float gamma = 1.f / (1.f + expf(-decayp[0]));
    const float lg = logf(gamma);

    const float* outB = outp + (size_t)b * TDIM * DDIM;
    const float* vB = vp + (size_t)b * TDIM * DDIM;

    const int c0 = ty * 4, e0 = tx * 4;
    float acc[4][4];
#pragma unroll
    for (int i = 0; i < 4; i++)
#pragma unroll
        for (int j = 0; j < 4; j++) acc[i][j] = 0.f;

    for (int ks = 0; ks < DDIM / 16; ks++) {
        {
            float4 r4 = *(const float4*)(outB + (size_t)(t0 + lc) * DDIM + ks * 16 + lq * 4);
            Rt[lq * 4 + 0][lc] = r4.x; Rt[lq * 4 + 1][lc] = r4.y;
            Rt[lq * 4 + 2][lc] = r4.z; Rt[lq * 4 + 3][lc] = r4.w;
            int tk = t0 + lc - 1;
            float4 k4 = make_float4(0.f, 0.f, 0.f, 0.f);
            if (tk >= 0) k4 = *(const float4*)(outB + (size_t)tk * DDIM + ks * 16 + lq * 4);
            Kt[lq * 4 + 0][lc] = k4.x; Kt[lq * 4 + 1][lc] = k4.y;
            Kt[lq * 4 + 2][lc] = k4.z; Kt[lq * 4 + 3][lc] = k4.w;
        }
        __syncthreads();
#pragma unroll
        for (int k = 0; k < 16; k++) {
            float4 a = *(const float4*)&Rt[k][c0];
            float4 bb = *(const float4*)&Kt[k][e0];
            acc[0][0] += a.x * bb.x; acc[0][1] += a.x * bb.y; acc[0][2] += a.x * bb.z; acc[0][3] += a.x * bb.w;
            acc[1][0] += a.y * bb.x; acc[1][1] += a.y * bb.y; acc[1][2] += a.y * bb.z; acc[1][3] += a.y * bb.w;
            acc[2][0] += a.z * bb.x; acc[2][1] += a.z * bb.y; acc[2][2] += a.z * bb.z; acc[2][3] += a.z * bb.w;
            acc[3][0] += a.w * bb.x; acc[3][1] += a.w * bb.y; acc[3][2] += a.w * bb.z; acc[3][3] += a.w * bb.w;
        }
        __syncthreads();
    }
#pragma unroll
    for (int i = 0; i < 4; i++)
#pragma unroll
        for (int j = 0; j < 4; j++) {
            int c = c0 + i, e = e0 + j;
            float mval = (c > e) ? expf(lg * (float)(c - 1 - e)) : 0.f;
            SMt[e][c] = acc[i][j] * mval;
        }
    __syncthreads();

    for (int db = 0; db < DDIM / 64; db++) {
#pragma unroll
        for (int i = 0; i < 4; i++)
            *(float4*)&Vs[lc][lq * 16 + i * 4] =
                *(const float4*)(vB + (size_t)(t0 + lc) * DDIM + db * 64 + lq * 16 + i * 4);
        __syncthreads();
        float a2[4][4];
#pragma unroll
        for (int i = 0; i < 4; i++)
#pragma unroll
            for (int j = 0; j < 4; j++) a2[i][j] = 0.f;
#pragma unroll 8
        for (int e = 0; e < 64; e++) {
            float4 a = *(const float4*)&SMt[e][c0];
            float4 bb = *(const float4*)&Vs[e][tx * 4];
            a2[0][0] += a.x * bb.x; a2[0][1] += a.x * bb.y; a2[0][2] += a.x * bb.z; a2[0][3] += a.x * bb.w;
            a2[1][0] += a.y * bb.x; a2[1][1] += a.y * bb.y; a2[1][2] += a.y * bb.z; a2[1][3] += a.y * bb.w;
            a2[2][0] += a.z * bb.x; a2[2][1] += a.z * bb.y; a2[2][2] += a.z * bb.z; a2[2][3] += a.z * bb.w;
            a2[3][0] += a.w * bb.x; a2[3][1] += a.w * bb.y; a2[3][2] += a.w * bb.z; a2[3][3] += a.w * bb.w;
        }
#pragma unroll
        for (int i = 0; i < 4; i++)
            *(float4*)(intrap + (size_t)b * TDIM * DDIM + (size_t)(t0 + c0 + i) * DDIM + db * 64 + tx * 4)
                = make_float4(a2[i][0], a2[i][1], a2[i][2], a2[i][3]);
        __syncthreads();
    }
}

// -------- recurrent scan: W tile [kk 256][dv 64] per CTA --------
#define SCAN_SMEM_FLOATS (256 * 64 + 256 * 68 + 64 * 260 + 64 * 68)

__global__ void __launch_bounds__(256) scan_kernel(const float* __restrict__ outp,
                                                   const float* __restrict__ vp,
                                                   float* __restrict__ interp,
                                                   const float* __restrict__ decayp)
{
    extern __shared__ float smf[];
    float* Wt = smf;
    float* Rt = Wt + 256 * 64;
    float* Ks = Rt + 256 * 68;
    float* Vg = Ks + 64 * 260;

    const int slab = blockIdx.x, dvb = blockIdx.y, b = blockIdx.z;
    const int kkbase = slab * 256, dvbase = dvb * 64;
    const int tid = threadIdx.x;
    const float gamma = 1.f / (1.f + expf(-decayp[0]));
    const float lg = logf(gamma);
    const float gC = expf(lg * 64.f);

    for (int i = tid; i < 256 * 64; i += 256) Wt[i] = 0.f;

    const float* outB = outp + (size_t)b * TDIM * DDIM;
    const float* vB = vp + (size_t)b * TDIM * DDIM;
    float* ipB = interp + (size_t)slab * ((size_t)MROWS * DDIM) + (size_t)b * TDIM * DDIM;

    const int tx = tid & 15, ty = tid >> 4;
    const int lc = tid >> 2, lq = tid & 3;
    const float gwc = expf(lg * (float)(63 - lc));
    __syncthreads();

    for (int ch = 0; ch < 64; ch++) {
        const int t0 = ch * 64;
        {
            const float* rrow = outB + (size_t)(t0 + lc) * DDIM + kkbase + lq * 64;
#pragma unroll
            for (int i = 0; i < 16; i++) {
                float4 v4 = *(const float4*)(rrow + i * 4);
                int kk = lq * 64 + i * 4;
                Rt[(kk + 0) * 68 + lc] = v4.x; Rt[(kk + 1) * 68 + lc] = v4.y;
                Rt[(kk + 2) * 68 + lc] = v4.z; Rt[(kk + 3) * 68 + lc] = v4.w;
            }
            int tk = t0 + lc - 1;
            if (tk >= 0) {
                const float* krow = outB + (size_t)tk * DDIM + kkbase + lq * 64;
#pragma unroll
                for (int i = 0; i < 16; i++)
                    *(float4*)&Ks[lc * 260 + lq * 64 + i * 4] = *(const float4*)(krow + i * 4);
            } else {
                float4 z = make_float4(0.f, 0.f, 0.f, 0.f);
#pragma unroll
                for (int i = 0; i < 16; i++)
                    *(float4*)&Ks[lc * 260 + lq * 64 + i * 4] = z;
            }
            const float* vrow = vB + (size_t)(t0 + lc) * DDIM + dvbase + lq * 16;
#pragma unroll
            for (int i = 0; i < 4; i++) {
                float4 v4 = *(const float4*)(vrow + i * 4);
                v4.x *= gwc; v4.y *= gwc; v4.z *= gwc; v4.w *= gwc;
                *(float4*)&Vg[lc * 68 + lq * 16 + i * 4] = v4;
            }
        }
        __syncthreads();
        {
            const int c0 = ty * 4, dv0 = tx * 4;
            float acc[4][4];
#pragma unroll
            for (int i = 0; i < 4; i++)
#pragma unroll
                for (int j = 0; j < 4; j++) acc[i][j] = 0.f;
#pragma unroll 4
            for (int k = 0; k < 256; k++) {
                float4 a = *(const float4*)&Rt[k * 68 + c0];
                float4 w = *(const float4*)&Wt[k * 64 + dv0];
                acc[0][0] += a.x * w.x; acc[0][1] += a.x * w.y; acc[0][2] += a.x * w.z; acc[0][3] += a.x * w.w;
                acc[1][0] += a.y * w.x; acc[1][1] += a.y * w.y; acc[1][2] += a.y * w.z; acc[1][3] += a.y * w.w;
                acc[2][0] += a.z * w.x; acc[2][1] += a.z * w.y; acc[2][2] += a.z * w.z; acc[2][3] += a.z * w.w;
                acc[3][0] += a.w * w.x; acc[3][1] += a.w * w.y; acc[3][2] += a.w * w.z; acc[3][3] += a.w * w.w;
            }
#pragma unroll
            for (int i = 0; i < 4; i++) {
                float gpc = expf(lg * (float)(c0 + i));
                *(float4*)(ipB + (size_t)(t0 + c0 + i) * DDIM + dvbase + dv0) =
                    make_float4(acc[i][0] * gpc, acc[i][1] * gpc, acc[i][2] * gpc, acc[i][3] * gpc);
            }
        }
        __syncthreads();
        {
            const int dv0 = tx * 4, kk0 = ty * 16;
            float acc[16][4];
#pragma unroll
            for (int i = 0; i < 16; i++)
#pragma unroll
                for (int j = 0; j < 4; j++) acc[i][j] = 0.f;
#pragma unroll 4
            for (int cc = 0; cc < 64; cc++) {
                float4 v4 = *(const float4*)&Vg[cc * 68 + dv0];
#pragma unroll
                for (int ii = 0; ii < 4; ii++) {
                    float4 k4 = *(const float4*)&Ks[cc * 260 + kk0 + ii * 4];
                    int r = ii * 4;
                    acc[r + 0][0] += k4.x * v4.x; acc[r + 0][1] += k4.x * v4.y; acc[r + 0][2] += k4.x * v4.z; acc[r + 0][3] += k4.x * v4.w;
                    acc[r + 1][0] += k4.y * v4.x; acc[r + 1][1] += k4.y * v4.y; acc[r + 1][2] += k4.y * v4.z; acc[r + 1][3] += k4.y * v4.w;
                    acc[r + 2][0] += k4.z * v4.x; acc[r + 2][1] += k4.z * v4.y; acc[r + 2][2] += k4.z * v4.z; acc[r + 2][3] += k4.z * v4.w;
                    acc[r + 3][0] += k4.w * v4.x; acc[r + 3][1] += k4.w * v4.y; acc[r + 3][2] += k4.w * v4.z; acc[r + 3][3] += k4.w * v4.w;
                }
            }
#pragma unroll
            for (int i = 0; i < 16; i++) {
                float4 w = *(float4*)&Wt[(kk0 + i) * 64 + dv0];
                w.x = w.x * gC + acc[i][0]; w.y = w.y * gC + acc[i][1];
                w.z = w.z * gC + acc[i][2]; w.w = w.w * gC + acc[i][3];
                *(float4*)&Wt[(kk0 + i) * 64 + dv0] = w;
            }
        }
        __syncthreads();
    }
}

// ================= host launcher =================
extern "C" void kernel_launch(void* const* d_in, const int* in_sizes, int n_in,
                              void* d_out, int out_size)
{
    (void)in_sizes; (void)n_in; (void)out_size;
    const float* x       = (const float*)d_in[0];
    const float* norm_w  = (const float*)d_in[1];
    const float* proj_w  = (const float*)d_in[2];
    const float* gate_w  = (const float*)d_in[3];
    const float* conv_w  = (const float*)d_in[4];
    const float* conv_b  = (const float*)d_in[5];
    const float* outpw   = (const float*)d_in[6];
    const float* write_w = (const float*)d_in[7];
    const float* read_w  = (const float*)d_in[8];
    const float* decay   = (const float*)d_in[9];
    const float* lalpha  = (const float*)d_in[10];
    float* outO = (float*)d_out;

    float *h, *val, *gs, *u, *o, *v, *intra, *interp;
    cudaGetSymbolAddress((void**)&h, g_h);
    cudaGetSymbolAddress((void**)&val, g_val);
    cudaGetSymbolAddress((void**)&gs, g_gs);
    cudaGetSymbolAddress((void**)&u, g_u);
    cudaGetSymbolAddress((void**)&o, g_out);
    cudaGetSymbolAddress((void**)&v, g_v);
    cudaGetSymbolAddress((void**)&intra, g_intra);
    cudaGetSymbolAddress((void**)&interp, g_interp);

    const float* nul = nullptr;
    const size_t SZ = (size_t)MROWS * DDIM;

    cudaFuncSetAttribute(mma_gemm<0>, cudaFuncAttributeMaxDynamicSharedMemorySize, MMA_SMEM);
    cudaFuncSetAttribute(mma_gemm<1>, cudaFuncAttributeMaxDynamicSharedMemorySize, MMA_SMEM);
    cudaFuncSetAttribute(mma_gemm<2>, cudaFuncAttributeMaxDynamicSharedMemorySize, MMA_SMEM);

    rmsnorm_kernel<<<MROWS, 256>>>(x, norm_w, h);

    // val = h @ proj_w^T
    mma_gemm<0><<<dim3(EDIM / 128, MROWS / 128), 256, MMA_SMEM>>>(
        h, proj_w, val, EDIM, DDIM, nul, nul, nul, nul, nul, nul);
    // gs = silu(h @ gate_w^T)
    mma_gemm<1><<<dim3(EDIM / 128, MROWS / 128), 256, MMA_SMEM>>>(
        h, gate_w, gs, EDIM, DDIM, nul, nul, nul, nul, nul, nul);
    // u = silu(conv(val)) * gs
    conv_kernel<<<dim3(EDIM / 256, MROWS / 64), 256>>>(val, gs, conv_w, conv_b, u);
    // o = u @ out_proj_w^T
    mma_gemm<0><<<dim3(DDIM / 128, MROWS / 128), 256, MMA_SMEM>>>(
        u, outpw, o, DDIM, EDIM, nul, nul, nul, nul, nul, nul);
    // v = o @ write_w^T
    mma_gemm<0><<<dim3(DDIM / 128, MROWS / 128), 256, MMA_SMEM>>>(
        o, write_w, v, DDIM, DDIM, nul, nul, nul, nul, nul, nul);

    intra_kernel<<<dim3(TDIM / 64, BDIM), 256>>>(o, v, intra, decay);

    const int scan_smem = SCAN_SMEM_FLOATS * 4;
    cudaFuncSetAttribute(scan_kernel, cudaFuncAttributeMaxDynamicSharedMemorySize, scan_smem);
    scan_kernel<<<dim3(3, DDIM / 64, BDIM), 256, scan_smem>>>(o, v, interp, decay);

    // out = x + o + exp(la) * ((intra + i0 + i1 + i2) @ read_w^T)
    mma_gemm<2><<<dim3(DDIM / 128, MROWS / 128), 256, MMA_SMEM>>>(
        intra, read_w, outO, DDIM, DDIM,
        interp, interp + SZ, interp + 2 * SZ, x, o, lalpha);
}